// round 1
// baseline (speedup 1.0000x reference)
#include <cuda_runtime.h>

#define T_STEPS 128
#define IN_DIM  32
#define HID     64
#define G4      256          // 4*HID gates
#define KDIM    96           // IN_DIM + HID
#define TB      64           // batches per block
#define SROW    72           // padded row stride of D (floats), 16B-aligned
#define NTHREADS 512
#define BATCH   8192

// scratch: x transposed to [T][IN][B] for coalesced per-step tile loads
__device__ float g_xT[(size_t)T_STEPS * IN_DIM * BATCH];

__global__ void transpose_x_kernel(const float* __restrict__ x) {
    __shared__ float tile[32][33];
    const int t  = blockIdx.y;
    const int b0 = blockIdx.x * 32;
    const int c  = threadIdx.x & 31;   // lane-fast index
    const int r0 = threadIdx.x >> 5;   // 0..7
#pragma unroll
    for (int r = 0; r < 4; ++r) {
        int row = r0 + r * 8;          // batch-within-tile 0..31
        // read x[b0+row][t][c]  (contiguous over c -> coalesced)
        tile[row][c] = x[((size_t)(b0 + row) * T_STEPS + t) * IN_DIM + c];
    }
    __syncthreads();
#pragma unroll
    for (int r = 0; r < 4; ++r) {
        int kk = r0 + r * 8;           // input dim 0..31
        // write xT[t][kk][b0+c]  (contiguous over c -> coalesced)
        g_xT[((size_t)t * IN_DIM + kk) * BATCH + b0 + c] = tile[c][kk];
    }
}

__device__ __forceinline__ float sigf(float x) {
    return __fdividef(1.0f, 1.0f + __expf(-x));
}
__device__ __forceinline__ float tanh_fast(float x) {
    return __fdividef(2.0f, 1.0f + __expf(-2.0f * x)) - 1.0f;
}

__global__ __launch_bounds__(NTHREADS)
void lstm_kernel(const float* __restrict__ W_ih, const float* __restrict__ W_hh,
                 const float* __restrict__ b_ih, const float* __restrict__ b_hh,
                 const float* __restrict__ W_fc, const float* __restrict__ b_fc,
                 float* __restrict__ out)
{
    extern __shared__ float smem[];
    float* Wt = smem;                  // [KDIM][G4]  weights, gate-interleaved
    float* D  = smem + KDIM * G4;      // [KDIM][SROW] rows 0..31: x_t ; rows 32..95: h

    const int tid = threadIdx.x;
    const int ty  = tid >> 3;          // hidden unit 0..63
    const int tx  = tid & 7;           // batch group 0..7
    const int b0  = blockIdx.x * TB;

    // ---- one-time: load & reorder weights: Wt[k][4*h+q] ----
    for (int idx = tid; idx < KDIM * G4; idx += NTHREADS) {
        int k   = idx >> 8;            // 0..95
        int col = idx & 255;
        int h   = col >> 2;
        int q   = col & 3;             // 0=i 1=f 2=g 3=o
        float v = (k < IN_DIM) ? W_ih[(q * HID + h) * IN_DIM + k]
                               : W_hh[(q * HID + h) * HID + (k - IN_DIM)];
        Wt[idx] = v;
    }
    // zero h region
    for (int idx = tid; idx < HID * TB; idx += NTHREADS) {
        D[(IN_DIM + (idx >> 6)) * SROW + (idx & 63)] = 0.0f;
    }

    float bias[4];
#pragma unroll
    for (int q = 0; q < 4; ++q) bias[q] = b_ih[q * HID + ty] + b_hh[q * HID + ty];

    // x tile prefetch: thread owns (kk, 4 batches) float4
    const int kk = tid >> 4;           // 0..31
    const int li = tid & 15;           // 0..15
    float4 xr = *(const float4*)&g_xT[((size_t)0 * IN_DIM + kk) * BATCH + b0 + 4 * li];

    __syncthreads();                   // weights + zeroed h visible
    *(float4*)&D[kk * SROW + 4 * li] = xr;                 // stage x_0
    xr = *(const float4*)&g_xT[((size_t)1 * IN_DIM + kk) * BATCH + b0 + 4 * li];
    __syncthreads();

    float c[8];
#pragma unroll
    for (int j = 0; j < 8; ++j) c[j] = 0.0f;

    const float* wp = Wt + 4 * ty;
    const float* dp = D + 4 * tx;

    for (int t = 0; t < T_STEPS; ++t) {
        float acc[4][8];
#pragma unroll
        for (int q = 0; q < 4; ++q)
#pragma unroll
            for (int j = 0; j < 8; ++j) acc[q][j] = bias[q];

#pragma unroll 4
        for (int k = 0; k < KDIM; ++k) {
            float4 w  = *(const float4*)(wp + k * G4);
            float4 d0 = *(const float4*)(dp + k * SROW);        // batches 4tx..4tx+3
            float4 d1 = *(const float4*)(dp + k * SROW + 32);   // batches 32+4tx..+3
            float wv[4] = {w.x, w.y, w.z, w.w};
            float dv[8] = {d0.x, d0.y, d0.z, d0.w, d1.x, d1.y, d1.z, d1.w};
#pragma unroll
            for (int q = 0; q < 4; ++q)
#pragma unroll
                for (int j = 0; j < 8; ++j) acc[q][j] += wv[q] * dv[j];
        }

        // elementwise update (fully register-resident)
        float hnew[8];
#pragma unroll
        for (int j = 0; j < 8; ++j) {
            float ig = sigf(acc[0][j]);
            float fg = sigf(acc[1][j]);
            float gg = tanh_fast(acc[2][j]);
            float og = sigf(acc[3][j]);
            float cn = fg * c[j] + ig * gg;
            c[j] = cn;
            hnew[j] = og * tanh_fast(cn);
        }

        __syncthreads();               // everyone done reading D
        *(float4*)&D[(IN_DIM + ty) * SROW + 4 * tx]      =
            make_float4(hnew[0], hnew[1], hnew[2], hnew[3]);
        *(float4*)&D[(IN_DIM + ty) * SROW + 4 * tx + 32] =
            make_float4(hnew[4], hnew[5], hnew[6], hnew[7]);
        if (t + 1 < T_STEPS) {
            *(float4*)&D[kk * SROW + 4 * li] = xr;   // stage x_{t+1}
            if (t + 2 < T_STEPS)
                xr = *(const float4*)&g_xT[((size_t)(t + 2) * IN_DIM + kk) * BATCH + b0 + 4 * li];
        }
        __syncthreads();
    }

    // ---- final FC: out[b][o] = b_fc[o] + sum_h W_fc[o][h] * h_T[b][h] ----
    const int ob = tid >> 3;           // batch 0..63
    const int oo = tid & 7;            // output 0..7
    float s = b_fc[oo];
#pragma unroll 8
    for (int h2 = 0; h2 < HID; ++h2)
        s += W_fc[oo * HID + h2] * D[(IN_DIM + h2) * SROW + ob];
    out[(size_t)(b0 + ob) * 8 + oo] = s;
}

extern "C" void kernel_launch(void* const* d_in, const int* in_sizes, int n_in,
                              void* d_out, int out_size)
{
    const float* x    = (const float*)d_in[0];
    const float* W_ih = (const float*)d_in[1];
    const float* W_hh = (const float*)d_in[2];
    const float* b_ih = (const float*)d_in[3];
    const float* b_hh = (const float*)d_in[4];
    const float* W_fc = (const float*)d_in[5];
    const float* b_fc = (const float*)d_in[6];
    float* out = (float*)d_out;

    dim3 tg(BATCH / 32, T_STEPS);
    transpose_x_kernel<<<tg, 256>>>(x);

    size_t smem = (size_t)(KDIM * G4 + KDIM * SROW) * sizeof(float);
    cudaFuncSetAttribute(lstm_kernel, cudaFuncAttributeMaxDynamicSharedMemorySize, (int)smem);
    lstm_kernel<<<BATCH / TB, NTHREADS, smem>>>(W_ih, W_hh, b_ih, b_hh, W_fc, b_fc, out);
}

// round 2
// speedup vs baseline: 1.2560x; 1.2560x over previous
#include <cuda_runtime.h>

#define T_STEPS 128
#define IN_DIM  32
#define HID     64
#define G4      256          // 4*HID gates
#define KDIM    96           // IN_DIM + HID
#define TB      64           // batches per block
#define SROW    72           // padded row stride of D (floats), 16B-aligned
#define DBUF    (KDIM * SROW)
#define NTHREADS 512
#define BATCH   8192

// scratch: x transposed to [T][IN][B] for coalesced per-step tile loads
__device__ float g_xT[(size_t)T_STEPS * IN_DIM * BATCH];

__global__ void transpose_x_kernel(const float* __restrict__ x) {
    __shared__ float tile[32][33];
    const int t  = blockIdx.y;
    const int b0 = blockIdx.x * 32;
    const int c  = threadIdx.x & 31;
    const int r0 = threadIdx.x >> 5;
#pragma unroll
    for (int r = 0; r < 4; ++r) {
        int row = r0 + r * 8;
        tile[row][c] = x[((size_t)(b0 + row) * T_STEPS + t) * IN_DIM + c];
    }
    __syncthreads();
#pragma unroll
    for (int r = 0; r < 4; ++r) {
        int kk = r0 + r * 8;
        g_xT[((size_t)t * IN_DIM + kk) * BATCH + b0 + c] = tile[c][kk];
    }
}

__device__ __forceinline__ float tanh_a(float x) {
    float y;
    asm("tanh.approx.f32 %0, %1;" : "=f"(y) : "f"(x));
    return y;
}
__device__ __forceinline__ float sig_a(float x) {
    return 0.5f + 0.5f * tanh_a(0.5f * x);
}
__device__ __forceinline__ unsigned long long pack2(float a, float b) {
    unsigned long long r;
    asm("mov.b64 %0, {%1, %2};" : "=l"(r)
        : "r"(__float_as_uint(a)), "r"(__float_as_uint(b)));
    return r;
}
__device__ __forceinline__ void unpack2(unsigned long long v, float& a, float& b) {
    unsigned int lo, hi;
    asm("mov.b64 {%0, %1}, %2;" : "=r"(lo), "=r"(hi) : "l"(v));
    a = __uint_as_float(lo);
    b = __uint_as_float(hi);
}
#define FMA2(acc, a, b) \
    asm("fma.rn.f32x2 %0, %1, %2, %0;" : "+l"(acc) : "l"(a), "l"(b))

__global__ __launch_bounds__(NTHREADS)
void lstm_kernel(const float* __restrict__ W_ih, const float* __restrict__ W_hh,
                 const float* __restrict__ b_ih, const float* __restrict__ b_hh,
                 const float* __restrict__ W_fc, const float* __restrict__ b_fc,
                 float* __restrict__ out)
{
    extern __shared__ float smem[];
    float* Wt = smem;                    // [KDIM][G4] weights, gate-interleaved
    float* D0 = smem + KDIM * G4;        // double-buffered [KDIM][SROW]
    float* D1 = D0 + DBUF;               // rows 0..31: x_t ; rows 32..95: h

    const int tid = threadIdx.x;
    const int ty  = tid >> 3;            // hidden unit 0..63
    const int tx  = tid & 7;             // batch group 0..7
    const int b0  = blockIdx.x * TB;

    // ---- one-time: load & reorder weights: Wt[k][4*h+q] ----
    for (int idx = tid; idx < KDIM * G4; idx += NTHREADS) {
        int k   = idx >> 8;
        int col = idx & 255;
        int h   = col >> 2;
        int q   = col & 3;               // 0=i 1=f 2=g 3=o
        float v = (k < IN_DIM) ? W_ih[(q * HID + h) * IN_DIM + k]
                               : W_hh[(q * HID + h) * HID + (k - IN_DIM)];
        Wt[idx] = v;
    }
    // zero h region of buffer 0 (read at t=0)
    for (int idx = tid; idx < HID * TB; idx += NTHREADS) {
        D0[(IN_DIM + (idx >> 6)) * SROW + (idx & 63)] = 0.0f;
    }

    unsigned long long bias2[4];
#pragma unroll
    for (int q = 0; q < 4; ++q) {
        float bq = b_ih[q * HID + ty] + b_hh[q * HID + ty];
        bias2[q] = pack2(bq, bq);
    }

    // x tile staging: thread owns (kk, 4 batches) float4
    const int kk = tid >> 4;             // 0..31
    const int li = tid & 15;             // 0..15
    float4 xr = *(const float4*)&g_xT[((size_t)0 * IN_DIM + kk) * BATCH + b0 + 4 * li];

    __syncthreads();                     // weights + zeroed h visible
    *(float4*)&D0[kk * SROW + 4 * li] = xr;            // stage x_0 into buf0
    xr = *(const float4*)&g_xT[((size_t)1 * IN_DIM + kk) * BATCH + b0 + 4 * li];
    __syncthreads();

    float c[8];
#pragma unroll
    for (int j = 0; j < 8; ++j) c[j] = 0.0f;

    const float* wp = Wt + 4 * ty;

    for (int t = 0; t < T_STEPS; ++t) {
        const float* cur = (t & 1) ? D1 : D0;
        float*       nxt = (t & 1) ? D0 : D1;
        const float* dp  = cur + 4 * tx;

        unsigned long long acc[4][4];    // [gate][batch-pair]
#pragma unroll
        for (int q = 0; q < 4; ++q)
#pragma unroll
            for (int p = 0; p < 4; ++p) acc[q][p] = bias2[q];

#pragma unroll 8
        for (int k = 0; k < KDIM; ++k) {
            float4 w = *(const float4*)(wp + k * G4);
            ulonglong2 dA = *(const ulonglong2*)(dp + k * SROW);       // batches 4tx..+3
            ulonglong2 dB = *(const ulonglong2*)(dp + k * SROW + 32);  // batches 32+4tx..+3
            unsigned long long w2;
            w2 = pack2(w.x, w.x);
            FMA2(acc[0][0], w2, dA.x); FMA2(acc[0][1], w2, dA.y);
            FMA2(acc[0][2], w2, dB.x); FMA2(acc[0][3], w2, dB.y);
            w2 = pack2(w.y, w.y);
            FMA2(acc[1][0], w2, dA.x); FMA2(acc[1][1], w2, dA.y);
            FMA2(acc[1][2], w2, dB.x); FMA2(acc[1][3], w2, dB.y);
            w2 = pack2(w.z, w.z);
            FMA2(acc[2][0], w2, dA.x); FMA2(acc[2][1], w2, dA.y);
            FMA2(acc[2][2], w2, dB.x); FMA2(acc[2][3], w2, dB.y);
            w2 = pack2(w.w, w.w);
            FMA2(acc[3][0], w2, dA.x); FMA2(acc[3][1], w2, dA.y);
            FMA2(acc[3][2], w2, dB.x); FMA2(acc[3][3], w2, dB.y);
        }

        // elementwise update (fully register-resident)
        float hnew[8];
#pragma unroll
        for (int p = 0; p < 4; ++p) {
            float i0, i1, f0, f1, g0, g1, o0, o1;
            unpack2(acc[0][p], i0, i1);
            unpack2(acc[1][p], f0, f1);
            unpack2(acc[2][p], g0, g1);
            unpack2(acc[3][p], o0, o1);
            int j = 2 * p;
            float cn0 = sig_a(f0) * c[j]     + sig_a(i0) * tanh_a(g0);
            float cn1 = sig_a(f1) * c[j + 1] + sig_a(i1) * tanh_a(g1);
            c[j]     = cn0;
            c[j + 1] = cn1;
            hnew[j]     = sig_a(o0) * tanh_a(cn0);
            hnew[j + 1] = sig_a(o1) * tanh_a(cn1);
        }

        // write into the OTHER buffer (current one still being read by peers)
        *(float4*)&nxt[(IN_DIM + ty) * SROW + 4 * tx] =
            make_float4(hnew[0], hnew[1], hnew[2], hnew[3]);
        *(float4*)&nxt[(IN_DIM + ty) * SROW + 4 * tx + 32] =
            make_float4(hnew[4], hnew[5], hnew[6], hnew[7]);
        if (t + 1 < T_STEPS) {
            *(float4*)&nxt[kk * SROW + 4 * li] = xr;    // stage x_{t+1}
            if (t + 2 < T_STEPS)
                xr = *(const float4*)&g_xT[((size_t)(t + 2) * IN_DIM + kk) * BATCH + b0 + 4 * li];
        }
        __syncthreads();                  // single barrier per step
    }

    // final h lives in buffer (T_STEPS & 1) == 0 -> D0
    // ---- final FC: out[b][o] = b_fc[o] + sum_h W_fc[o][h] * h_T[b][h] ----
    const int ob = tid >> 3;             // batch 0..63
    const int oo = tid & 7;              // output 0..7
    float s = b_fc[oo];
#pragma unroll 8
    for (int h2 = 0; h2 < HID; ++h2)
        s += W_fc[oo * HID + h2] * D0[(IN_DIM + h2) * SROW + ob];
    out[(size_t)(b0 + ob) * 8 + oo] = s;
}

extern "C" void kernel_launch(void* const* d_in, const int* in_sizes, int n_in,
                              void* d_out, int out_size)
{
    const float* x    = (const float*)d_in[0];
    const float* W_ih = (const float*)d_in[1];
    const float* W_hh = (const float*)d_in[2];
    const float* b_ih = (const float*)d_in[3];
    const float* b_hh = (const float*)d_in[4];
    const float* W_fc = (const float*)d_in[5];
    const float* b_fc = (const float*)d_in[6];
    float* out = (float*)d_out;

    dim3 tg(BATCH / 32, T_STEPS);
    transpose_x_kernel<<<tg, 256>>>(x);

    size_t smem = (size_t)(KDIM * G4 + 2 * DBUF) * sizeof(float);
    cudaFuncSetAttribute(lstm_kernel, cudaFuncAttributeMaxDynamicSharedMemorySize, (int)smem);
    lstm_kernel<<<BATCH / TB, NTHREADS, smem>>>(W_ih, W_hh, b_ih, b_hh, W_fc, b_fc, out);
}